// round 1
// baseline (speedup 1.0000x reference)
#include <cuda_runtime.h>
#include <math.h>

#define S   512
#define T   16384
#define D   512
#define DFF 2048
#define MAXF 1024
#define EPS 1e-5f

// ---------------- device scratch (no allocs allowed) ----------------
__device__ int   g_seg_start[S + 3];
__device__ float g_ctx[S * D];        // relu(ctx)
__device__ float g_x[S * D];          // x = LN(tgt + tgt2)
__device__ float g_h[S * DFF];        // relu(x@W1^T+b1)
__device__ float g_pre[S * D];        // pre-LN buffer for stage 2
__device__ float g_part[2 * S * D];   // split-K partials for FFN2

// ---------------- K0: segment boundary scan ----------------
__global__ void seg_kernel(const int* __restrict__ aidx) {
    __shared__ int s_cnt[512];
    __shared__ int s_off[512];
    int tid = threadIdx.x;
    const int CH = T / 512;       // 32 frames per thread
    int t0 = tid * CH;
    int c = 0;
    for (int i = 0; i < CH; i++) {
        int t = t0 + i;
        if (t > 0 && aidx[t] != aidx[t - 1]) c++;
    }
    s_cnt[tid] = c;
    __syncthreads();
    if (tid == 0) {
        int acc = 0;
        for (int i = 0; i < 512; i++) { s_off[i] = acc; acc += s_cnt[i]; }
    }
    __syncthreads();
    for (int g = tid; g < S + 3; g += 512) g_seg_start[g] = T;  // default: past-the-end
    __syncthreads();
    int seg = s_off[tid];
    for (int i = 0; i < CH; i++) {
        int t = t0 + i;
        if (t == 0) {
            g_seg_start[0] = 0;
        } else if (aidx[t] != aidx[t - 1]) {
            seg++;
            if (seg < S + 3) g_seg_start[seg] = t;
        }
    }
}

// ---------------- K1: banded attention, one block per query ----------------
__global__ __launch_bounds__(256) void attn_kernel(
    const float* __restrict__ tgt, const float* __restrict__ memory,
    const float* __restrict__ pos, const float* __restrict__ qpos)
{
    int s = blockIdx.x;
    int tid = threadIdx.x;
    __shared__ float qs[D];
    __shared__ float sc[MAXF];
    __shared__ float red[16];

    int lo = g_seg_start[s > 0 ? s - 1 : 0];
    int hi = g_seg_start[s + 2];
    if (hi > T) hi = T;
    int nF = hi - lo;
    if (nF > MAXF) nF = MAXF;   // safety cap (96 expected)

    qs[tid]       = tgt[s * D + tid]       + qpos[s * D + tid];
    qs[tid + 256] = tgt[s * D + tid + 256] + qpos[s * D + tid + 256];
    __syncthreads();

    int warp = tid >> 5, lane = tid & 31;

    // scores: one warp per frame
    for (int j = warp; j < nF; j += 8) {
        const float* mrow = memory + (size_t)(lo + j) * D;
        const float* prow = pos    + (size_t)(lo + j) * D;
        float sum = 0.f;
        #pragma unroll
        for (int d = lane; d < D; d += 32)
            sum += qs[d] * (mrow[d] + prow[d]);
        #pragma unroll
        for (int o = 16; o; o >>= 1) sum += __shfl_xor_sync(0xffffffffu, sum, o);
        if (lane == 0) sc[j] = sum * 0.04419417382415922f;  // 1/sqrt(512)
    }
    __syncthreads();

    // softmax: max
    float mx = -1e30f;
    for (int j = tid; j < nF; j += 256) mx = fmaxf(mx, sc[j]);
    #pragma unroll
    for (int o = 16; o; o >>= 1) mx = fmaxf(mx, __shfl_xor_sync(0xffffffffu, mx, o));
    if (lane == 0) red[warp] = mx;
    __syncthreads();
    if (tid == 0) {
        float m = red[0];
        for (int w = 1; w < 8; w++) m = fmaxf(m, red[w]);
        red[0] = m;
    }
    __syncthreads();
    mx = red[0];
    __syncthreads();

    // exp + sum
    float ssum = 0.f;
    for (int j = tid; j < nF; j += 256) {
        float e = __expf(sc[j] - mx);
        sc[j] = e;
        ssum += e;
    }
    #pragma unroll
    for (int o = 16; o; o >>= 1) ssum += __shfl_xor_sync(0xffffffffu, ssum, o);
    if (lane == 0) red[8 + warp] = ssum;
    __syncthreads();
    if (tid == 0) {
        float m = 0.f;
        for (int w = 0; w < 8; w++) m += red[8 + w];
        red[8] = 1.0f / m;
    }
    __syncthreads();
    float inv = red[8];

    // ctx = sum_j p_j * memory[lo+j], then relu
    float a0 = 0.f, a1 = 0.f;
    for (int j = 0; j < nF; j++) {
        const float* mrow = memory + (size_t)(lo + j) * D;
        float p = sc[j];
        a0 += p * mrow[tid];
        a1 += p * mrow[tid + 256];
    }
    g_ctx[s * D + tid]       = fmaxf(a0 * inv, 0.f);
    g_ctx[s * D + tid + 256] = fmaxf(a1 * inv, 0.f);
}

// ---------------- Tiled NT GEMM: out[m,n] = sum_k A[m,k]*W[n,k] (+bias,+res,relu) ----------------
// grid: (N/BN, M/BM, nsplit); split-K writes out + z*M*N with kbeg = z*kl.
template<int BM, int BN, int TM, int TN>
__global__ __launch_bounds__(256) void gemm_nt(
    const float* __restrict__ A, const float* __restrict__ W,
    const float* __restrict__ bias, const float* __restrict__ res,
    float* __restrict__ out, int M, int N, int K, int kl, int do_relu)
{
    static_assert((BM / TM) * (BN / TN) == 256, "256 threads");
    __shared__ float sA[16][BM];
    __shared__ float sB[16][BN];

    int tid = threadIdx.x;
    int m0 = blockIdx.y * BM;
    int n0 = blockIdx.x * BN;
    int z  = blockIdx.z;
    int kbeg = z * kl;
    float* outp = out + (size_t)z * M * N;

    int tx = tid % (BN / TN);
    int ty = tid / (BN / TN);

    float acc[TM][TN];
    #pragma unroll
    for (int i = 0; i < TM; i++)
        #pragma unroll
        for (int j = 0; j < TN; j++) acc[i][j] = 0.f;

    for (int kt = 0; kt < kl; kt += 16) {
        // load A tile
        #pragma unroll
        for (int idx = tid; idx < BM * 16; idx += 256) {
            int m = idx >> 4, k = idx & 15;
            sA[k][m] = A[(size_t)(m0 + m) * K + kbeg + kt + k];
        }
        // load W tile
        #pragma unroll
        for (int idx = tid; idx < BN * 16; idx += 256) {
            int n = idx >> 4, k = idx & 15;
            sB[k][n] = W[(size_t)(n0 + n) * K + kbeg + kt + k];
        }
        __syncthreads();
        #pragma unroll
        for (int k = 0; k < 16; k++) {
            float a[TM], b[TN];
            #pragma unroll
            for (int i = 0; i < TM; i++) a[i] = sA[k][ty * TM + i];
            #pragma unroll
            for (int j = 0; j < TN; j++) b[j] = sB[k][tx * TN + j];
            #pragma unroll
            for (int i = 0; i < TM; i++)
                #pragma unroll
                for (int j = 0; j < TN; j++) acc[i][j] += a[i] * b[j];
        }
        __syncthreads();
    }

    #pragma unroll
    for (int i = 0; i < TM; i++) {
        int m = m0 + ty * TM + i;
        #pragma unroll
        for (int j = 0; j < TN; j++) {
            int n = n0 + tx * TN + j;
            float v = acc[i][j];
            if (bias) v += bias[n];
            if (res)  v += res[(size_t)m * N + n];
            if (do_relu) v = fmaxf(v, 0.f);
            outp[(size_t)m * N + n] = v;
        }
    }
}

// ---------------- LayerNorm (optionally fusing split-K reduce + bias + residual) ----------------
__global__ __launch_bounds__(256) void ln_kernel(
    const float* __restrict__ y0, const float* __restrict__ y1,
    const float* __restrict__ bias, const float* __restrict__ res,
    const float* __restrict__ g, const float* __restrict__ b,
    float* __restrict__ out)
{
    int row = blockIdx.x, tid = threadIdx.x;
    int i0 = row * D + tid, i1 = i0 + 256;
    float v0 = y0[i0], v1 = y0[i1];
    if (y1)  { v0 += y1[i0];        v1 += y1[i1]; }
    if (bias){ v0 += bias[tid];     v1 += bias[tid + 256]; }
    if (res) { v0 += res[i0];       v1 += res[i1]; }

    __shared__ float red[8];
    int warp = tid >> 5, lane = tid & 31;

    float sum = v0 + v1;
    #pragma unroll
    for (int o = 16; o; o >>= 1) sum += __shfl_xor_sync(0xffffffffu, sum, o);
    if (lane == 0) red[warp] = sum;
    __syncthreads();
    if (tid == 0) {
        float s = 0.f;
        for (int w = 0; w < 8; w++) s += red[w];
        red[0] = s * (1.0f / D);
    }
    __syncthreads();
    float mu = red[0];
    __syncthreads();

    float d0 = v0 - mu, d1 = v1 - mu;
    float sq = d0 * d0 + d1 * d1;
    #pragma unroll
    for (int o = 16; o; o >>= 1) sq += __shfl_xor_sync(0xffffffffu, sq, o);
    if (lane == 0) red[warp] = sq;
    __syncthreads();
    if (tid == 0) {
        float s = 0.f;
        for (int w = 0; w < 8; w++) s += red[w];
        red[0] = rsqrtf(s * (1.0f / D) + EPS);
    }
    __syncthreads();
    float r = red[0];

    out[i0] = d0 * r * g[tid]       + b[tid];
    out[i1] = d1 * r * g[tid + 256] + b[tid + 256];
}

// ---------------- launch ----------------
extern "C" void kernel_launch(void* const* d_in, const int* in_sizes, int n_in,
                              void* d_out, int out_size)
{
    const float* tgt     = (const float*)d_in[0];
    const float* memory  = (const float*)d_in[1];
    const float* pos     = (const float*)d_in[2];
    const float* qpos    = (const float*)d_in[3];
    const int*   aidx    = (const int*)  d_in[4];
    const float* W_tgt2  = (const float*)d_in[5];
    const float* b_tgt2  = (const float*)d_in[6];
    const float* W1      = (const float*)d_in[7];
    const float* b1      = (const float*)d_in[8];
    const float* W2      = (const float*)d_in[9];
    const float* b2      = (const float*)d_in[10];
    const float* g2      = (const float*)d_in[11];
    const float* be2     = (const float*)d_in[12];
    const float* g3      = (const float*)d_in[13];
    const float* be3     = (const float*)d_in[14];
    float* out = (float*)d_out;

    float *p_ctx, *p_x, *p_h, *p_pre, *p_part;
    cudaGetSymbolAddress((void**)&p_ctx,  g_ctx);
    cudaGetSymbolAddress((void**)&p_x,    g_x);
    cudaGetSymbolAddress((void**)&p_h,    g_h);
    cudaGetSymbolAddress((void**)&p_pre,  g_pre);
    cudaGetSymbolAddress((void**)&p_part, g_part);

    // K0: segment table
    seg_kernel<<<1, 512>>>(aidx);

    // K1: banded attention -> relu(ctx)
    attn_kernel<<<S, 256>>>(tgt, memory, pos, qpos);

    // K2: tgt2 = ctx @ W_tgt2^T + b_tgt2 + tgt   (pre-LN)
    gemm_nt<32, 64, 2, 4><<<dim3(D / 64, S / 32, 1), 256>>>(
        p_ctx, W_tgt2, b_tgt2, tgt, p_pre, S, D, D, D, 0);

    // LN2 -> x
    ln_kernel<<<S, 256>>>(p_pre, nullptr, nullptr, nullptr, g2, be2, p_x);

    // K3: h = relu(x @ W1^T + b1)
    gemm_nt<64, 64, 4, 4><<<dim3(DFF / 64, S / 64, 1), 256>>>(
        p_x, W1, b1, nullptr, p_h, S, DFF, D, D, 1);

    // K4: FFN2 split-K=2 partials (deterministic)
    gemm_nt<32, 64, 2, 4><<<dim3(D / 64, S / 32, 2), 256>>>(
        p_h, W2, nullptr, nullptr, p_part, S, D, DFF, DFF / 2, 0);

    // LN3: reduce partials + b2 + x residual -> out
    ln_kernel<<<S, 256>>>(p_part, p_part + S * D, b2, p_x, g3, be3, out);
}

// round 5
// speedup vs baseline: 2.4525x; 2.4525x over previous
#include <cuda_runtime.h>
#include <stdint.h>
#include <math.h>

#define S   512
#define T   16384
#define D   512
#define DFF 2048
#define EPS 1e-5f
#define QB  4          // queries per attention block
#define WMAX 384       // max frames in a 6-segment window (192 nominal)

// ---------------- device scratch (no allocs allowed) ----------------
__device__ int   g_seg_start[S + 3];
__device__ float g_ctx[S * D];        // relu(ctx)
__device__ float g_x[S * D];          // x = LN(tgt + tgt2)
__device__ float g_h[S * DFF];        // relu(x@W1^T+b1)
__device__ float g_pre[S * D];        // pre-LN buffer for stage 2
__device__ float g_part[2 * S * D];   // split-K partials for FFN2

// ---------------- helpers ----------------
__device__ __forceinline__ float cvt_tf32(float x) {
    unsigned int u;
    asm("cvt.rna.tf32.f32 %0, %1;" : "=r"(u) : "f"(x));
    return __uint_as_float(u);
}

__device__ __forceinline__ void mma_tf32(float c[4],
                                         unsigned int a0, unsigned int a1,
                                         unsigned int a2, unsigned int a3,
                                         unsigned int b0, unsigned int b1) {
    asm volatile(
        "mma.sync.aligned.m16n8k8.row.col.f32.tf32.tf32.f32 "
        "{%0,%1,%2,%3}, {%4,%5,%6,%7}, {%8,%9}, {%0,%1,%2,%3};\n"
        : "+f"(c[0]), "+f"(c[1]), "+f"(c[2]), "+f"(c[3])
        : "r"(a0), "r"(a1), "r"(a2), "r"(a3), "r"(b0), "r"(b1));
}

// ---------------- K0: segment boundary scan ----------------
__global__ void seg_kernel(const int* __restrict__ aidx) {
    __shared__ int s_cnt[512];
    __shared__ int s_off[512];
    int tid = threadIdx.x;
    const int CH = T / 512;
    int t0 = tid * CH;
    int c = 0;
    for (int i = 0; i < CH; i++) {
        int t = t0 + i;
        if (t > 0 && aidx[t] != aidx[t - 1]) c++;
    }
    s_cnt[tid] = c;
    __syncthreads();
    if (tid == 0) {
        int acc = 0;
        for (int i = 0; i < 512; i++) { s_off[i] = acc; acc += s_cnt[i]; }
    }
    __syncthreads();
    for (int g = tid; g < S + 3; g += 512) g_seg_start[g] = T;
    __syncthreads();
    int seg = s_off[tid];
    for (int i = 0; i < CH; i++) {
        int t = t0 + i;
        if (t == 0) {
            g_seg_start[0] = 0;
        } else if (aidx[t] != aidx[t - 1]) {
            seg++;
            if (seg < S + 3) g_seg_start[seg] = t;
        }
    }
}

// ---------------- K1: banded attention, QB queries per block ----------------
__global__ __launch_bounds__(256) void attn_kernel(
    const float* __restrict__ tgt, const float* __restrict__ memory,
    const float* __restrict__ pos, const float* __restrict__ qpos)
{
    int q0 = blockIdx.x * QB;
    int tid = threadIdx.x;
    int warp = tid >> 5, lane = tid & 31;

    __shared__ float qs[QB][D];      // 8 KB
    __shared__ float sc[QB][WMAX];   // 6 KB
    __shared__ float redm[QB][9];
    __shared__ float reds[QB][9];

    int lo = g_seg_start[q0 > 0 ? q0 - 1 : 0];
    int hi = g_seg_start[q0 + QB + 1];
    if (hi > T) hi = T;
    int nF = hi - lo;
    if (nF > WMAX) nF = WMAX;

    int qlo[QB], qhi[QB];
    #pragma unroll
    for (int q = 0; q < QB; q++) {
        int qq = q0 + q;
        qlo[q] = g_seg_start[qq > 0 ? qq - 1 : 0];
        int h = g_seg_start[qq + 2];
        qhi[q] = h > T ? T : h;
    }

    // load QB query vectors (tgt + query_pos) into smem
    for (int idx = tid; idx < QB * D; idx += 256) {
        int q = idx >> 9, d = idx & (D - 1);
        qs[q][d] = tgt[(q0 + q) * D + d] + qpos[(q0 + q) * D + d];
    }
    __syncthreads();

    const float scale = 0.04419417382415922f;  // 1/sqrt(512)

    // scores: one warp per frame; each frame's (m+p) row loaded ONCE, dotted vs 4 queries
    for (int j = warp; j < nF; j += 8) {
        const float4* m4 = (const float4*)(memory + (size_t)(lo + j) * D);
        const float4* p4 = (const float4*)(pos    + (size_t)(lo + j) * D);
        float s[QB] = {0.f, 0.f, 0.f, 0.f};
        #pragma unroll
        for (int c = 0; c < 4; c++) {
            int d4 = c * 32 + lane;
            float4 mv = m4[d4];
            float4 pv = p4[d4];
            float4 kv = make_float4(mv.x + pv.x, mv.y + pv.y, mv.z + pv.z, mv.w + pv.w);
            #pragma unroll
            for (int q = 0; q < QB; q++) {
                float4 qv = ((const float4*)qs[q])[d4];
                s[q] += qv.x * kv.x + qv.y * kv.y + qv.z * kv.z + qv.w * kv.w;
            }
        }
        #pragma unroll
        for (int q = 0; q < QB; q++) {
            #pragma unroll
            for (int o = 16; o; o >>= 1) s[q] += __shfl_xor_sync(0xffffffffu, s[q], o);
        }
        if (lane == 0) {
            int tglob = lo + j;
            #pragma unroll
            for (int q = 0; q < QB; q++)
                sc[q][j] = (tglob >= qlo[q] && tglob < qhi[q]) ? s[q] * scale : -INFINITY;
        }
    }
    __syncthreads();

    // softmax (4 queries simultaneously)
    float mx[QB] = {-INFINITY, -INFINITY, -INFINITY, -INFINITY};
    for (int j = tid; j < nF; j += 256) {
        #pragma unroll
        for (int q = 0; q < QB; q++) mx[q] = fmaxf(mx[q], sc[q][j]);
    }
    #pragma unroll
    for (int q = 0; q < QB; q++) {
        #pragma unroll
        for (int o = 16; o; o >>= 1) mx[q] = fmaxf(mx[q], __shfl_xor_sync(0xffffffffu, mx[q], o));
        if (lane == 0) redm[q][warp] = mx[q];
    }
    __syncthreads();
    if (tid < QB) {
        float m = redm[tid][0];
        for (int w = 1; w < 8; w++) m = fmaxf(m, redm[tid][w]);
        redm[tid][8] = m;
    }
    __syncthreads();
    #pragma unroll
    for (int q = 0; q < QB; q++) mx[q] = redm[q][8];

    float ssum[QB] = {0.f, 0.f, 0.f, 0.f};
    for (int j = tid; j < nF; j += 256) {
        #pragma unroll
        for (int q = 0; q < QB; q++) {
            float e = __expf(sc[q][j] - mx[q]);
            sc[q][j] = e;
            ssum[q] += e;
        }
    }
    #pragma unroll
    for (int q = 0; q < QB; q++) {
        #pragma unroll
        for (int o = 16; o; o >>= 1) ssum[q] += __shfl_xor_sync(0xffffffffu, ssum[q], o);
        if (lane == 0) reds[q][warp] = ssum[q];
    }
    __syncthreads();
    if (tid < QB) {
        float m = 0.f;
        for (int w = 0; w < 8; w++) m += reds[tid][w];
        reds[tid][8] = 1.0f / m;
    }
    __syncthreads();

    // ctx: each thread owns a float2 column pair, loops frames once for all 4 queries
    float2 a[QB];
    #pragma unroll
    for (int q = 0; q < QB; q++) a[q] = make_float2(0.f, 0.f);

    #pragma unroll 4
    for (int j = 0; j < nF; j++) {
        float2 mv = *(const float2*)(memory + (size_t)(lo + j) * D + 2 * tid);
        #pragma unroll
        for (int q = 0; q < QB; q++) {
            float p = sc[q][j];
            a[q].x += p * mv.x;
            a[q].y += p * mv.y;
        }
    }
    #pragma unroll
    for (int q = 0; q < QB; q++) {
        float inv = reds[q][8];
        float2 o;
        o.x = fmaxf(a[q].x * inv, 0.f);
        o.y = fmaxf(a[q].y * inv, 0.f);
        *(float2*)(g_ctx + (size_t)(q0 + q) * D + 2 * tid) = o;
    }
}

// ---------------- tf32 tensor-core NT GEMM: out[m,n] = sum_k A[m,k]*W[n,k] ----------------
// block tile 64x64, BK=32, double-buffered. grid: (N/64, M/64, nsplit)
#define SAK 36   // smem row stride (floats): 4g+t bank pattern is conflict-free
__global__ __launch_bounds__(256) void gemm_tf32(
    const float* __restrict__ A, const float* __restrict__ W,
    const float* __restrict__ bias, const float* __restrict__ res,
    float* __restrict__ out, int M, int N, int K, int kl, int do_relu)
{
    __shared__ float sA[2][64 * SAK];
    __shared__ float sW[2][64 * SAK];

    int tid = threadIdx.x;
    int m0 = blockIdx.y * 64;
    int n0 = blockIdx.x * 64;
    int z  = blockIdx.z;
    int kbeg = z * kl;
    float* outp = out + (size_t)z * M * N;

    int warp = tid >> 5, lane = tid & 31;
    int wm = warp >> 2, wn = warp & 3;    // 2x4 warp grid
    int g = lane >> 2, t = lane & 3;

    float acc[2][2][4];
    #pragma unroll
    for (int mi = 0; mi < 2; mi++)
        #pragma unroll
        for (int ni = 0; ni < 2; ni++)
            #pragma unroll
            for (int i = 0; i < 4; i++) acc[mi][ni][i] = 0.f;

    int r0 = tid >> 3;            // 0..31
    int c4 = (tid & 7) * 4;       // 0..28
    const float* Ap0 = A + (size_t)(m0 + r0) * K + kbeg + c4;
    const float* Ap1 = Ap0 + (size_t)32 * K;
    const float* Wp0 = W + (size_t)(n0 + r0) * K + kbeg + c4;
    const float* Wp1 = Wp0 + (size_t)32 * K;

    int NT = kl >> 5;

    // preload tile 0
    {
        float4 a0v = *(const float4*)Ap0;
        float4 a1v = *(const float4*)Ap1;
        float4 w0v = *(const float4*)Wp0;
        float4 w1v = *(const float4*)Wp1;
        float* dA0 = &sA[0][r0 * SAK + c4];
        float* dA1 = &sA[0][(r0 + 32) * SAK + c4];
        float* dW0 = &sW[0][r0 * SAK + c4];
        float* dW1 = &sW[0][(r0 + 32) * SAK + c4];
        dA0[0] = cvt_tf32(a0v.x); dA0[1] = cvt_tf32(a0v.y); dA0[2] = cvt_tf32(a0v.z); dA0[3] = cvt_tf32(a0v.w);
        dA1[0] = cvt_tf32(a1v.x); dA1[1] = cvt_tf32(a1v.y); dA1[2] = cvt_tf32(a1v.z); dA1[3] = cvt_tf32(a1v.w);
        dW0[0] = cvt_tf32(w0v.x); dW0[1] = cvt_tf32(w0v.y); dW0[2] = cvt_tf32(w0v.z); dW0[3] = cvt_tf32(w0v.w);
        dW1[0] = cvt_tf32(w1v.x); dW1[1] = cvt_tf32(w1v.y); dW1[2] = cvt_tf32(w1v.z); dW1[3] = cvt_tf32(w1v.w);
    }
    __syncthreads();

    for (int tt = 0; tt < NT; tt++) {
        int p = tt & 1;
        float4 na0, na1, nw0, nw1;
        if (tt + 1 < NT) {
            int ko = (tt + 1) * 32;
            na0 = *(const float4*)(Ap0 + ko);
            na1 = *(const float4*)(Ap1 + ko);
            nw0 = *(const float4*)(Wp0 + ko);
            nw1 = *(const float4*)(Wp1 + ko);
        }

        const float* pA = sA[p];
        const float* pW = sW[p];
        #pragma unroll
        for (int kk = 0; kk < 32; kk += 8) {
            unsigned int af[2][4], bf[2][2];
            #pragma unroll
            for (int mi = 0; mi < 2; mi++) {
                int mb = wm * 32 + mi * 16;
                af[mi][0] = __float_as_uint(pA[(mb + g) * SAK + kk + t]);
                af[mi][1] = __float_as_uint(pA[(mb + g + 8) * SAK + kk + t]);
                af[mi][2] = __float_as_uint(pA[(mb + g) * SAK + kk + t + 4]);
                af[mi][3] = __float_as_uint(pA[(mb + g + 8) * SAK + kk + t + 4]);
            }
            #pragma unroll
            for (int ni = 0; ni < 2; ni++) {
                int nb = wn * 16 + ni * 8;
                bf[ni][0] = __float_as_uint(pW[(nb + g) * SAK + kk + t]);
                bf[ni][1] = __float_as_uint(pW[(nb + g) * SAK + kk + t + 4]);
            }
            #pragma unroll
            for (int mi = 0; mi < 2; mi++)
                #pragma unroll
                for (int ni = 0; ni < 2; ni++)
                    mma_tf32(acc[mi][ni],
                             af[mi][0], af[mi][1], af[mi][2], af[mi][3],
                             bf[ni][0], bf[ni][1]);
        }

        if (tt + 1 < NT) {
            int pn = p ^ 1;
            float* dA0 = &sA[pn][r0 * SAK + c4];
            float* dA1 = &sA[pn][(r0 + 32) * SAK + c4];
            float* dW0 = &sW[pn][r0 * SAK + c4];
            float* dW1 = &sW[pn][(r0 + 32) * SAK + c4];
            dA0[0] = cvt_tf32(na0.x); dA0[1] = cvt_tf32(na0.y); dA0[2] = cvt_tf32(na0.z); dA0[3] = cvt_tf32(na0.w);
            dA1[0] = cvt_tf32(na1.x); dA1[1] = cvt_tf32(na1.y); dA1[2] = cvt_tf32(na1.z); dA1[3] = cvt_tf32(na1.w);
            dW0[0] = cvt_tf32(nw0.x); dW0[1] = cvt_tf32(nw0.y); dW0[2] = cvt_tf32(nw0.z); dW0[3] = cvt_tf32(nw0.w);
            dW1[0] = cvt_tf32(nw1.x); dW1[1] = cvt_tf32(nw1.y); dW1[2] = cvt_tf32(nw1.z); dW1[3] = cvt_tf32(nw1.w);
        }
        __syncthreads();
    }

    // epilogue
    #pragma unroll
    for (int mi = 0; mi < 2; mi++) {
        #pragma unroll
        for (int ni = 0; ni < 2; ni++) {
            int row = m0 + wm * 32 + mi * 16 + g;
            int col = n0 + wn * 16 + ni * 8 + 2 * t;
            float bx = 0.f, by = 0.f;
            if (bias) { bx = bias[col]; by = bias[col + 1]; }

            float v0 = acc[mi][ni][0] + bx;
            float v1 = acc[mi][ni][1] + by;
            if (res) { v0 += res[(size_t)row * N + col]; v1 += res[(size_t)row * N + col + 1]; }
            if (do_relu) { v0 = fmaxf(v0, 0.f); v1 = fmaxf(v1, 0.f); }
            *(float2*)(outp + (size_t)row * N + col) = make_float2(v0, v1);

            int row2 = row + 8;
            float v2 = acc[mi][ni][2] + bx;
            float v3 = acc[mi][ni][3] + by;
            if (res) { v2 += res[(size_t)row2 * N + col]; v3 += res[(size_t)row2 * N + col + 1]; }
            if (do_relu) { v2 = fmaxf(v2, 0.f); v3 = fmaxf(v3, 0.f); }
            *(float2*)(outp + (size_t)row2 * N + col) = make_float2(v2, v3);
        }
    }
}

// ---------------- LayerNorm: warp per row, values in registers ----------------
__global__ __launch_bounds__(256) void ln_kernel(
    const float* __restrict__ y0, const float* __restrict__ y1,
    const float* __restrict__ bias, const float* __restrict__ res,
    const float* __restrict__ g, const float* __restrict__ b,
    float* __restrict__ out)
{
    int warp = threadIdx.x >> 5, lane = threadIdx.x & 31;
    int row = blockIdx.x * 8 + warp;
    size_t base = (size_t)row * D;

    float v[16];
    #pragma unroll
    for (int i = 0; i < 4; i++) {
        int c = (lane + i * 32) * 4;
        float4 t0 = *(const float4*)(y0 + base + c);
        v[i * 4 + 0] = t0.x; v[i * 4 + 1] = t0.y; v[i * 4 + 2] = t0.z; v[i * 4 + 3] = t0.w;
        if (y1) {
            float4 t1 = *(const float4*)(y1 + base + c);
            v[i * 4 + 0] += t1.x; v[i * 4 + 1] += t1.y; v[i * 4 + 2] += t1.z; v[i * 4 + 3] += t1.w;
        }
        if (bias) {
            float4 t1 = *(const float4*)(bias + c);
            v[i * 4 + 0] += t1.x; v[i * 4 + 1] += t1.y; v[i * 4 + 2] += t1.z; v[i * 4 + 3] += t1.w;
        }
        if (res) {
            float4 t1 = *(const float4*)(res + base + c);
            v[i * 4 + 0] += t1.x; v[i * 4 + 1] += t1.y; v[i * 4 + 2] += t1.z; v[i * 4 + 3] += t1.w;
        }
    }

    float sum = 0.f;
    #pragma unroll
    for (int i = 0; i < 16; i++) sum += v[i];
    #pragma unroll
    for (int o = 16; o; o >>= 1) sum += __shfl_xor_sync(0xffffffffu, sum, o);
    float mu = sum * (1.0f / D);

    float sq = 0.f;
    #pragma unroll
    for (int i = 0; i < 16; i++) { float d = v[i] - mu; sq += d * d; }
    #pragma unroll
    for (int o = 16; o; o >>= 1) sq += __shfl_xor_sync(0xffffffffu, sq, o);
    float r = rsqrtf(sq * (1.0f / D) + EPS);

    #pragma unroll
    for (int i = 0; i < 4; i++) {
        int c = (lane + i * 32) * 4;
        float4 gv = *(const float4*)(g + c);
        float4 bv = *(const float4*)(b + c);
        float4 o;
        o.x = (v[i * 4 + 0] - mu) * r * gv.x + bv.x;
        o.y = (v[i * 4 + 1] - mu) * r * gv.y + bv.y;
        o.z = (v[i * 4 + 2] - mu) * r * gv.z + bv.z;
        o.w = (v[i * 4 + 3] - mu) * r * gv.w + bv.w;
        *(float4*)(out + base + c) = o;
    }
}

// ---------------- launch ----------------
extern "C" void kernel_launch(void* const* d_in, const int* in_sizes, int n_in,
                              void* d_out, int out_size)
{
    const float* tgt     = (const float*)d_in[0];
    const float* memory  = (const float*)d_in[1];
    const float* pos     = (const float*)d_in[2];
    const float* qpos    = (const float*)d_in[3];
    const int*   aidx    = (const int*)  d_in[4];
    const float* W_tgt2  = (const float*)d_in[5];
    const float* b_tgt2  = (const float*)d_in[6];
    const float* W1      = (const float*)d_in[7];
    const float* b1      = (const float*)d_in[8];
    const float* W2      = (const float*)d_in[9];
    const float* b2      = (const float*)d_in[10];
    const float* g2      = (const float*)d_in[11];
    const float* be2     = (const float*)d_in[12];
    const float* g3      = (const float*)d_in[13];
    const float* be3     = (const float*)d_in[14];
    float* out = (float*)d_out;

    float *p_ctx, *p_x, *p_h, *p_pre, *p_part;
    cudaGetSymbolAddress((void**)&p_ctx,  g_ctx);
    cudaGetSymbolAddress((void**)&p_x,    g_x);
    cudaGetSymbolAddress((void**)&p_h,    g_h);
    cudaGetSymbolAddress((void**)&p_pre,  g_pre);
    cudaGetSymbolAddress((void**)&p_part, g_part);

    // K0: segment table
    seg_kernel<<<1, 512>>>(aidx);

    // K1: banded attention -> relu(ctx), 4 queries per block
    attn_kernel<<<S / QB, 256>>>(tgt, memory, pos, qpos);

    // K2: tgt2 = ctx @ W_tgt2^T + b_tgt2 + tgt   (pre-LN)
    gemm_tf32<<<dim3(D / 64, S / 64, 1), 256>>>(
        p_ctx, W_tgt2, b_tgt2, tgt, p_pre, S, D, D, D, 0);

    // LN2 -> x
    ln_kernel<<<S / 8, 256>>>(p_pre, nullptr, nullptr, nullptr, g2, be2, p_x);

    // K3: h = relu(x @ W1^T + b1)
    gemm_tf32<<<dim3(DFF / 64, S / 64, 1), 256>>>(
        p_x, W1, b1, nullptr, p_h, S, DFF, D, D, 1);

    // K4: FFN2 split-K=2 partials (deterministic)
    gemm_tf32<<<dim3(D / 64, S / 64, 2), 256>>>(
        p_h, W2, nullptr, nullptr, p_part, S, D, DFF, DFF / 2, 0);

    // LN3: reduce partials + b2 + x residual -> out
    ln_kernel<<<S / 8, 256>>>(p_part, p_part + S * D, b2, p_x, g3, be3, out);
}